// round 3
// baseline (speedup 1.0000x reference)
#include <cuda_runtime.h>

// ---------------------------------------------------------------------------
// PlanStructuredNetwork: leaf MLP (32->128->128->32) over B*1024 rows, then a
// 10-level binary tree of join MLPs (96->128->128->32). fp32, fused per-level
// kernels with persistent CTAs and SMEM-resident weights; inner loops use
// packed fma.rn.f32x2 (FFMA2) for 2x fp32 throughput on sm_103a.
// ---------------------------------------------------------------------------

#define BATCH 2048
#define NLEAF 1024

// Scratch ping-pong buffers (static __device__: allocation-free).
__device__ float g_bufA[(size_t)BATCH * NLEAF * 32];      // 256 MB
__device__ float g_bufB[(size_t)BATCH * (NLEAF / 2) * 32]; // 128 MB

// ---- f32x2 helpers ---------------------------------------------------------
__device__ __forceinline__ unsigned long long bcast2(float x) {
    unsigned long long r;
    asm("mov.b64 %0, {%1, %1};" : "=l"(r) : "r"(__float_as_uint(x)));
    return r;
}
__device__ __forceinline__ void ffma2(unsigned long long& d,
                                      unsigned long long a,
                                      unsigned long long b) {
    asm("fma.rn.f32x2 %0, %1, %2, %0;" : "+l"(d) : "l"(a), "l"(b));
}
__device__ __forceinline__ void unpack2(unsigned long long v, float& lo, float& hi) {
    unsigned int l, h;
    asm("mov.b64 {%0, %1}, %2;" : "=r"(l), "=r"(h) : "l"(v));
    lo = __uint_as_float(l);
    hi = __uint_as_float(h);
}

// ---- dense layer: [64 x KK] @ [KK x 128] -> [64 x 128] (stride 132), +bias, relu
// Thread mapping: 256 threads, each computes a 4-row x 8-col tile.
// Warp covers 8 col-groups x 4 row-groups => W row reads are 128B-distinct
// (4-way broadcast) per LDS.128 -> ~1 crossbar cycle each.
template <int KK, int XSS, bool RELU>
__device__ __forceinline__ void dense_h(const float* __restrict__ Xs,
                                        const float* __restrict__ W,
                                        const float* __restrict__ bias,
                                        float* __restrict__ Out) {
    const int tid  = threadIdx.x;
    const int lane = tid & 31;
    const int w    = tid >> 5;
    const int cgrp = (lane & 7) | ((w & 1) << 3);        // 0..15
    const int rgrp = ((lane >> 3) & 3) | ((w >> 1) << 2); // 0..15
    const int col0 = cgrp * 8;
    const int row0 = rgrp * 4;

    unsigned long long acc[4][4];
#pragma unroll
    for (int i = 0; i < 4; i++)
#pragma unroll
        for (int j = 0; j < 4; j++) acc[i][j] = 0ull;

#pragma unroll 2
    for (int k0 = 0; k0 < KK; k0 += 4) {
        float4 a4[4];
#pragma unroll
        for (int i = 0; i < 4; i++)
            a4[i] = *(const float4*)(Xs + (row0 + i) * XSS + k0);
#pragma unroll
        for (int kk = 0; kk < 4; kk++) {
            const float* wr = W + (k0 + kk) * 128 + col0;
            ulonglong2 w01 = *(const ulonglong2*)(wr);
            ulonglong2 w23 = *(const ulonglong2*)(wr + 4);
            unsigned long long wp0 = w01.x, wp1 = w01.y, wp2 = w23.x, wp3 = w23.y;
#pragma unroll
            for (int i = 0; i < 4; i++) {
                float a = ((const float*)&a4[i])[kk];
                unsigned long long av = bcast2(a);
                ffma2(acc[i][0], av, wp0);
                ffma2(acc[i][1], av, wp1);
                ffma2(acc[i][2], av, wp2);
                ffma2(acc[i][3], av, wp3);
            }
        }
    }

#pragma unroll
    for (int i = 0; i < 4; i++) {
        float o[8];
#pragma unroll
        for (int j = 0; j < 4; j++) {
            float lo, hi;
            unpack2(acc[i][j], lo, hi);
            lo += bias[col0 + 2 * j];
            hi += bias[col0 + 2 * j + 1];
            if (RELU) { lo = fmaxf(lo, 0.f); hi = fmaxf(hi, 0.f); }
            o[2 * j] = lo;
            o[2 * j + 1] = hi;
        }
        float4* p = (float4*)(Out + (row0 + i) * 132 + col0);
        p[0] = make_float4(o[0], o[1], o[2], o[3]);
        p[1] = make_float4(o[4], o[5], o[6], o[7]);
    }
}

// ---- output layer: [64 x 128] (stride 132) @ [128 x 32] -> global [64 x 32]
__device__ __forceinline__ void dense_out(const float* __restrict__ Xs,
                                          const float* __restrict__ W,
                                          const float* __restrict__ bias,
                                          float* __restrict__ gout,
                                          long grow0) {
    const int tid  = threadIdx.x;
    const int c    = tid & 7;   // 8 col groups of 4
    const int r    = tid >> 3;  // 32 row groups of 2
    const int col0 = c * 4;
    const int row0 = r * 2;

    unsigned long long acc[2][2];
    acc[0][0] = acc[0][1] = acc[1][0] = acc[1][1] = 0ull;

#pragma unroll 4
    for (int k0 = 0; k0 < 128; k0 += 4) {
        float4 a0 = *(const float4*)(Xs + row0 * 132 + k0);
        float4 a1 = *(const float4*)(Xs + (row0 + 1) * 132 + k0);
#pragma unroll
        for (int kk = 0; kk < 4; kk++) {
            ulonglong2 wv = *(const ulonglong2*)(W + (k0 + kk) * 32 + col0);
            unsigned long long av0 = bcast2(((const float*)&a0)[kk]);
            unsigned long long av1 = bcast2(((const float*)&a1)[kk]);
            ffma2(acc[0][0], av0, wv.x);
            ffma2(acc[0][1], av0, wv.y);
            ffma2(acc[1][0], av1, wv.x);
            ffma2(acc[1][1], av1, wv.y);
        }
    }

#pragma unroll
    for (int i = 0; i < 2; i++) {
        float lo0, hi0, lo1, hi1;
        unpack2(acc[i][0], lo0, hi0);
        unpack2(acc[i][1], lo1, hi1);
        lo0 += bias[col0 + 0];
        hi0 += bias[col0 + 1];
        lo1 += bias[col0 + 2];
        hi1 += bias[col0 + 3];
        *(float4*)(gout + (grow0 + row0 + i) * 32 + col0) =
            make_float4(lo0, hi0, lo1, hi1);
    }
}

// ---- fused 3-layer MLP kernel (K = input width: 32 leaf / 96 join) ---------
template <int K>
__global__ void __launch_bounds__(256, 1)
mlp_kernel(const float* __restrict__ feats,  // leaf_feats (K=32) or internal_feats (K=96)
           const float* __restrict__ prev,   // previous level output (B, 2n, 32); unused for leaf
           const float* __restrict__ gW1, const float* __restrict__ gb1,
           const float* __restrict__ gW2, const float* __restrict__ gb2,
           const float* __restrict__ gW3, const float* __restrict__ gb3,
           float* __restrict__ outp,         // (B, n, 32) contiguous
           int n, int ln, int off, int num_tiles) {
    constexpr int XSS = K + 4;  // padded xs row stride (words)
    extern __shared__ float sm[];
    float* sW1 = sm;                 // K*128
    float* sW2 = sW1 + K * 128;      // 128*128
    float* sW3 = sW2 + 128 * 128;    // 128*32
    float* sb1 = sW3 + 128 * 32;     // 128
    float* sb2 = sb1 + 128;          // 128
    float* sb3 = sb2 + 128;          // 32
    float* xs  = sb3 + 32;           // 64*XSS
    float* hA  = xs + 64 * XSS;      // 64*132
    float* hB  = hA + 64 * 132;      // 64*132

    // Load weights once per (persistent) CTA.
    const int tid = threadIdx.x;
    {
        for (int i = tid * 4; i < K * 128; i += 1024)
            *(float4*)(sW1 + i) = *(const float4*)(gW1 + i);
        for (int i = tid * 4; i < 128 * 128; i += 1024)
            *(float4*)(sW2 + i) = *(const float4*)(gW2 + i);
        for (int i = tid * 4; i < 128 * 32; i += 1024)
            *(float4*)(sW3 + i) = *(const float4*)(gW3 + i);
        for (int i = tid * 4; i < 128; i += 1024)
            *(float4*)(sb1 + i) = *(const float4*)(gb1 + i);
        for (int i = tid * 4; i < 128; i += 1024)
            *(float4*)(sb2 + i) = *(const float4*)(gb2 + i);
        for (int i = tid * 4; i < 32; i += 1024)
            *(float4*)(sb3 + i) = *(const float4*)(gb3 + i);
    }
    __syncthreads();

    for (int t = blockIdx.x; t < num_tiles; t += gridDim.x) {
        long row0g = (long)t * 64;

        // Stage the 64-row input tile into SMEM.
        if constexpr (K == 32) {
#pragma unroll
            for (int idx = tid; idx < 64 * 8; idx += 256) {
                int row = idx >> 3, j = idx & 7;
                float4 v = *(const float4*)(feats + (row0g + row) * 32 + j * 4);
                *(float4*)(xs + row * XSS + j * 4) = v;
            }
        } else {
            for (int idx = tid; idx < 64 * 24; idx += 256) {
                int row = idx / 24, j = idx % 24;
                long rg = row0g + row;
                int b = (int)(rg >> ln);
                int i = (int)(rg & (long)(n - 1));
                float4 v;
                if (j < 8)
                    v = *(const float4*)(feats + ((long)b * (NLEAF - 1) + off + i) * 32 + j * 4);
                else
                    v = *(const float4*)(prev + ((long)b * n + i) * 64 + (j - 8) * 4);
                *(float4*)(xs + row * XSS + j * 4) = v;
            }
        }
        __syncthreads();

        dense_h<K, XSS, true>(xs, sW1, sb1, hA);
        __syncthreads();
        dense_h<128, 132, true>(hA, sW2, sb2, hB);
        __syncthreads();
        dense_out(hB, sW3, sb3, outp, row0g);
        __syncthreads();
    }
}

__global__ void gather_kernel(const float* __restrict__ src, float* __restrict__ dst) {
    int i = blockIdx.x * blockDim.x + threadIdx.x;
    if (i < BATCH) dst[i] = src[(long)i * 32];
}

static size_t smem_bytes_for(int K) {
    return ((size_t)(K + 128) * 128 + 128 * 32 + 288 + 64 * (K + 4) + 2 * 64 * 132) *
           sizeof(float);
}

extern "C" void kernel_launch(void* const* d_in, const int* in_sizes, int n_in,
                              void* d_out, int out_size) {
    (void)in_sizes; (void)n_in; (void)out_size;
    const float* leaf_feats     = (const float*)d_in[0];
    const float* internal_feats = (const float*)d_in[1];
    const float* sW1 = (const float*)d_in[2];
    const float* sb1 = (const float*)d_in[3];
    const float* sW2 = (const float*)d_in[4];
    const float* sb2 = (const float*)d_in[5];
    const float* sW3 = (const float*)d_in[6];
    const float* sb3 = (const float*)d_in[7];
    const float* jW1 = (const float*)d_in[8];
    const float* jb1 = (const float*)d_in[9];
    const float* jW2 = (const float*)d_in[10];
    const float* jb2 = (const float*)d_in[11];
    const float* jW3 = (const float*)d_in[12];
    const float* jb3 = (const float*)d_in[13];
    float* out = (float*)d_out;

    float *pa = nullptr, *pb = nullptr;
    cudaGetSymbolAddress((void**)&pa, g_bufA);
    cudaGetSymbolAddress((void**)&pb, g_bufB);

    int dev = 0, sms = 148;
    cudaGetDevice(&dev);
    cudaDeviceGetAttribute(&sms, cudaDevAttrMultiProcessorCount, dev);

    size_t smem32 = smem_bytes_for(32);
    size_t smem96 = smem_bytes_for(96);
    cudaFuncSetAttribute(mlp_kernel<32>, cudaFuncAttributeMaxDynamicSharedMemorySize,
                         (int)smem32);
    cudaFuncSetAttribute(mlp_kernel<96>, cudaFuncAttributeMaxDynamicSharedMemorySize,
                         (int)smem96);

    // Leaf level: (B*1024, 32) -> bufA as (B, 1024, 32)
    {
        int tiles = (BATCH * NLEAF) / 64;
        int grid = tiles < sms ? tiles : sms;
        mlp_kernel<32><<<grid, 256, smem32>>>(leaf_feats, nullptr,
                                              sW1, sb1, sW2, sb2, sW3, sb3,
                                              pa, NLEAF, 10, 0, tiles);
    }

    // Join levels: n = 512 .. 1
    const float* prev = pa;
    float* curb = pb;
    int off = 0;
    for (int n = NLEAF / 2, ln = 9; n >= 1; n >>= 1, --ln) {
        int tiles = (BATCH * n) / 64;
        int grid = tiles < sms ? tiles : sms;
        mlp_kernel<96><<<grid, 256, smem96>>>(internal_feats, prev,
                                              jW1, jb1, jW2, jb2, jW3, jb3,
                                              curb, n, ln, off, tiles);
        off += n;
        const float* tmp = curb;
        curb = (float*)prev;
        prev = tmp;
    }

    // Final: out[b] = last_level[b, 0, 0]
    gather_kernel<<<(BATCH + 255) / 256, 256>>>(prev, out);
}

// round 7
// speedup vs baseline: 3.6984x; 3.6984x over previous
#include <cuda_runtime.h>
#include <cuda_bf16.h>
#include <cstdint>

// ---------------------------------------------------------------------------
// PlanStructuredNetwork via warp-level bf16 mma.sync (sm_103-safe: no 'a'
// features). 3-term split-bf16 (xh*wh + xh*wl + xl*wh), fp32 accumulate.
// 128-row tiles, 8 warps x 16 rows; L1->L2->L3 chained entirely in registers
// (mma D-fragment layout == next A-fragment layout). Weights hi/lo in SMEM,
// B fragments via ldmatrix.x4 with odd-16B-stride padding (conflict-free).
// ---------------------------------------------------------------------------

#define BATCH 2048
#define NLEAF 1024

__device__ float g_bufA[(size_t)BATCH * NLEAF * 32];       // 256 MB
__device__ float g_bufB[(size_t)BATCH * (NLEAF / 2) * 32]; // 128 MB

__device__ __forceinline__ uint32_t smem_u32(const void* p) {
    uint32_t a;
    asm("{ .reg .u64 t; cvta.to.shared.u64 t, %1; cvt.u32.u64 %0, t; }"
        : "=r"(a) : "l"(p));
    return a;
}

__device__ __forceinline__ void ldsm4(uint32_t addr, uint32_t& r0, uint32_t& r1,
                                      uint32_t& r2, uint32_t& r3) {
    asm volatile("ldmatrix.sync.aligned.m8n8.x4.shared.b16 {%0,%1,%2,%3}, [%4];"
                 : "=r"(r0), "=r"(r1), "=r"(r2), "=r"(r3) : "r"(addr));
}

__device__ __forceinline__ void mma16816(float* d, const uint32_t* a,
                                         uint32_t b0, uint32_t b1) {
    asm volatile(
        "mma.sync.aligned.m16n8k16.row.col.f32.bf16.bf16.f32 "
        "{%0,%1,%2,%3}, {%4,%5,%6,%7}, {%8,%9}, {%0,%1,%2,%3};"
        : "+f"(d[0]), "+f"(d[1]), "+f"(d[2]), "+f"(d[3])
        : "r"(a[0]), "r"(a[1]), "r"(a[2]), "r"(a[3]), "r"(b0), "r"(b1));
}

// split a,b into bf16 hi pair + bf16 residual-lo pair
__device__ __forceinline__ void pack_split(float a, float b, uint32_t& hi, uint32_t& lo) {
    __nv_bfloat16 ha = __float2bfloat16(a), hb = __float2bfloat16(b);
    __nv_bfloat162 hp(ha, hb);
    hi = *reinterpret_cast<uint32_t*>(&hp);
    __nv_bfloat162 lp = __floats2bfloat162_rn(a - __bfloat162float(ha),
                                              b - __bfloat162float(hb));
    lo = *reinterpret_cast<uint32_t*>(&lp);
}

// D(acc) + bias [-> relu] -> next-layer A fragments (hi/lo), all in registers.
template <bool RELU>
__device__ __forceinline__ void epi(const float (&acc)[16][4],
                                    uint32_t (&ah)[8][4], uint32_t (&al)[8][4],
                                    const float* __restrict__ bias, int lane4) {
#pragma unroll
    for (int j = 0; j < 16; j++) {
        float2 bb = *(const float2*)(bias + 8 * j + lane4);
        float c0 = acc[j][0] + bb.x, c1 = acc[j][1] + bb.y;
        float c2 = acc[j][2] + bb.x, c3 = acc[j][3] + bb.y;
        if (RELU) {
            c0 = fmaxf(c0, 0.f); c1 = fmaxf(c1, 0.f);
            c2 = fmaxf(c2, 0.f); c3 = fmaxf(c3, 0.f);
        }
        const int s = j >> 1, o = (j & 1) * 2;
        pack_split(c0, c1, ah[s][o], al[s][o]);
        pack_split(c2, c3, ah[s][o + 1], al[s][o + 1]);
    }
}

template <int K>
__global__ void __launch_bounds__(256, 1)
mlp_mma(const float* __restrict__ feats, const float* __restrict__ prev,
        const float* __restrict__ gW1, const float* __restrict__ gb1,
        const float* __restrict__ gW2, const float* __restrict__ gb2,
        const float* __restrict__ gW3, const float* __restrict__ gb3,
        float* __restrict__ outp, int n, int ln, int offv, int num_tiles) {
    constexpr int SA = K + 8;   // halves/row for A,W1 (odd multiple of 8 -> conflict-free)
    constexpr int S2 = 136;     // halves/row for W2,W3
    constexpr int S1 = K / 16;  // layer-1 k-steps
    // SMEM layout (offsets in halves; all byte offsets multiple of 16)
    constexpr int O_W1H = 0;
    constexpr int O_W1L = O_W1H + 128 * SA;
    constexpr int O_W2H = O_W1L + 128 * SA;
    constexpr int O_W2L = O_W2H + 128 * S2;
    constexpr int O_W3H = O_W2L + 128 * S2;
    constexpr int O_W3L = O_W3H + 32 * S2;
    constexpr int O_AH  = O_W3L + 32 * S2;
    constexpr int O_AL  = O_AH + 128 * SA;
    constexpr int O_BIAS = O_AL + 128 * SA;

    extern __shared__ __nv_bfloat16 sh[];
    float* bs = (float*)(sh + O_BIAS);  // [0..127]=b1 [128..255]=b2 [256..287]=b3
    const int tid = threadIdx.x;
    const int lane = tid & 31;
    const int wid = tid >> 5;

    // ---- stage weights (transposed: Wt[n][k]) as bf16 hi + residual lo ------
    for (int idx = tid; idx < 128 * K; idx += 256) {
        int nn = idx & 127, kk = idx >> 7;
        float w = gW1[kk * 128 + nn];
        __nv_bfloat16 h = __float2bfloat16(w);
        sh[O_W1H + nn * SA + kk] = h;
        sh[O_W1L + nn * SA + kk] = __float2bfloat16(w - __bfloat162float(h));
    }
    for (int idx = tid; idx < 128 * 128; idx += 256) {
        int nn = idx & 127, kk = idx >> 7;
        float w = gW2[kk * 128 + nn];
        __nv_bfloat16 h = __float2bfloat16(w);
        sh[O_W2H + nn * S2 + kk] = h;
        sh[O_W2L + nn * S2 + kk] = __float2bfloat16(w - __bfloat162float(h));
    }
    for (int idx = tid; idx < 32 * 128; idx += 256) {
        int nn = idx & 31, kk = idx >> 5;
        float w = gW3[kk * 32 + nn];
        __nv_bfloat16 h = __float2bfloat16(w);
        sh[O_W3H + nn * S2 + kk] = h;
        sh[O_W3L + nn * S2 + kk] = __float2bfloat16(w - __bfloat162float(h));
    }
    if (tid < 128) { bs[tid] = gb1[tid]; bs[128 + tid] = gb2[tid]; }
    if (tid < 32)  bs[256 + tid] = gb3[tid];
    __syncthreads();

    const uint32_t sb = smem_u32(sh);
    const int lane4 = (lane & 3) * 2;
    // A-ldmatrix lane geometry (mats: rows 0-7/8-15 x cols 0-7/8-15)
    const int arow = lane & 15;
    const int acb  = ((lane >> 4) & 1) * 8;          // halves
    // B-ldmatrix lane geometry (mats: n 0-7/8-15 x k 0-7/8-15)
    const int bnr = (lane & 7) + ((lane >> 4) & 1) * 8;
    const int bkb = ((lane >> 3) & 1) * 8;           // halves
    const int mrow = wid * 16;                       // this warp's rows

    float acc[16][4];
    uint32_t ah[8][4], al[8][4];

    for (int t = blockIdx.x; t < num_tiles; t += gridDim.x) {
        long row0g = (long)t * 128;

        // ---- stage X: fp32 -> split bf16 hi/lo into SMEM A ------------------
        constexpr int CHN = K / 8;
        for (int idx = tid; idx < 128 * CHN; idx += 256) {
            int row = idx / CHN, c = idx % CHN;
            long rg = row0g + row;
            const float* src;
            if constexpr (K == 32) {
                src = feats + rg * 32 + c * 8;
            } else {
                int b = (int)(rg >> ln), i = (int)(rg & (long)(n - 1));
                if (c < 4)
                    src = feats + ((long)b * (NLEAF - 1) + offv + i) * 32 + c * 8;
                else
                    src = prev + ((long)b * n + i) * 64 + (c - 4) * 8;
            }
            float4 v0 = *(const float4*)src;
            float4 v1 = *(const float4*)(src + 4);
            uint32_t h[4], l[4];
            pack_split(v0.x, v0.y, h[0], l[0]);
            pack_split(v0.z, v0.w, h[1], l[1]);
            pack_split(v1.x, v1.y, h[2], l[2]);
            pack_split(v1.z, v1.w, h[3], l[3]);
            *(uint4*)((char*)sh + (O_AH + row * SA) * 2 + c * 16) =
                make_uint4(h[0], h[1], h[2], h[3]);
            *(uint4*)((char*)sh + (O_AL + row * SA) * 2 + c * 16) =
                make_uint4(l[0], l[1], l[2], l[3]);
        }
        __syncthreads();

        // ---- layer 1: A from SMEM -------------------------------------------
#pragma unroll
        for (int j = 0; j < 16; j++) {
            acc[j][0] = 0.f; acc[j][1] = 0.f; acc[j][2] = 0.f; acc[j][3] = 0.f;
        }
#pragma unroll
        for (int pass = 0; pass < 2; pass++) {
            const uint32_t bbase = sb + (pass ? O_W1L : O_W1H) * 2;
#pragma unroll
            for (int s = 0; s < S1; s++) {
                uint32_t a_h[4], a_l[4];
                ldsm4(sb + (O_AH + (mrow + arow) * SA) * 2 + (16 * s + acb) * 2,
                      a_h[0], a_h[1], a_h[2], a_h[3]);
                if (pass == 0)
                    ldsm4(sb + (O_AL + (mrow + arow) * SA) * 2 + (16 * s + acb) * 2,
                          a_l[0], a_l[1], a_l[2], a_l[3]);
#pragma unroll
                for (int j2 = 0; j2 < 8; j2++) {
                    uint32_t b0, b1, b2, b3;
                    ldsm4(bbase + ((16 * j2 + bnr) * SA + 16 * s + bkb) * 2,
                          b0, b1, b2, b3);
                    mma16816(acc[2 * j2],     a_h, b0, b1);
                    mma16816(acc[2 * j2 + 1], a_h, b2, b3);
                    if (pass == 0) {
                        mma16816(acc[2 * j2],     a_l, b0, b1);
                        mma16816(acc[2 * j2 + 1], a_l, b2, b3);
                    }
                }
            }
        }
        epi<true>(acc, ah, al, bs, lane4);

        // ---- layer 2: A from registers --------------------------------------
#pragma unroll
        for (int j = 0; j < 16; j++) {
            acc[j][0] = 0.f; acc[j][1] = 0.f; acc[j][2] = 0.f; acc[j][3] = 0.f;
        }
#pragma unroll
        for (int pass = 0; pass < 2; pass++) {
            const uint32_t bbase = sb + (pass ? O_W2L : O_W2H) * 2;
#pragma unroll
            for (int s = 0; s < 8; s++) {
#pragma unroll
                for (int j2 = 0; j2 < 8; j2++) {
                    uint32_t b0, b1, b2, b3;
                    ldsm4(bbase + ((16 * j2 + bnr) * S2 + 16 * s + bkb) * 2,
                          b0, b1, b2, b3);
                    mma16816(acc[2 * j2],     ah[s], b0, b1);
                    mma16816(acc[2 * j2 + 1], ah[s], b2, b3);
                    if (pass == 0) {
                        mma16816(acc[2 * j2],     al[s], b0, b1);
                        mma16816(acc[2 * j2 + 1], al[s], b2, b3);
                    }
                }
            }
        }
        epi<true>(acc, ah, al, bs + 128, lane4);

        // ---- layer 3: N=32, no relu, fp32 -> global -------------------------
#pragma unroll
        for (int j = 0; j < 4; j++) {
            acc[j][0] = 0.f; acc[j][1] = 0.f; acc[j][2] = 0.f; acc[j][3] = 0.f;
        }
#pragma unroll
        for (int pass = 0; pass < 2; pass++) {
            const uint32_t bbase = sb + (pass ? O_W3L : O_W3H) * 2;
#pragma unroll
            for (int s = 0; s < 8; s++) {
#pragma unroll
                for (int j2 = 0; j2 < 2; j2++) {
                    uint32_t b0, b1, b2, b3;
                    ldsm4(bbase + ((16 * j2 + bnr) * S2 + 16 * s + bkb) * 2,
                          b0, b1, b2, b3);
                    mma16816(acc[2 * j2],     ah[s], b0, b1);
                    mma16816(acc[2 * j2 + 1], ah[s], b2, b3);
                    if (pass == 0) {
                        mma16816(acc[2 * j2],     al[s], b0, b1);
                        mma16816(acc[2 * j2 + 1], al[s], b2, b3);
                    }
                }
            }
        }
#pragma unroll
        for (int j = 0; j < 4; j++) {
            float2 bb = *(const float2*)(bs + 256 + 8 * j + lane4);
            long r0 = row0g + mrow + (lane >> 2);
            float2 v0 = make_float2(acc[j][0] + bb.x, acc[j][1] + bb.y);
            float2 v1 = make_float2(acc[j][2] + bb.x, acc[j][3] + bb.y);
            *(float2*)(outp + r0 * 32 + 8 * j + lane4) = v0;
            *(float2*)(outp + (r0 + 8) * 32 + 8 * j + lane4) = v1;
        }
        __syncthreads();
    }
}

__global__ void gather_kernel(const float* __restrict__ src, float* __restrict__ dst) {
    int i = blockIdx.x * blockDim.x + threadIdx.x;
    if (i < BATCH) dst[i] = src[(long)i * 32];
}

static int smem_bytes(int K) {
    int SA = K + 8;
    int halves = 4 * 128 * SA /*W1 h/l + A h/l*/ + 2 * 128 * 136 + 2 * 32 * 136;
    return halves * 2 + 288 * 4;
}

extern "C" void kernel_launch(void* const* d_in, const int* in_sizes, int n_in,
                              void* d_out, int out_size) {
    (void)in_sizes; (void)n_in; (void)out_size;
    const float* leaf_feats     = (const float*)d_in[0];
    const float* internal_feats = (const float*)d_in[1];
    const float* sW1 = (const float*)d_in[2];
    const float* sb1 = (const float*)d_in[3];
    const float* sW2 = (const float*)d_in[4];
    const float* sb2 = (const float*)d_in[5];
    const float* sW3 = (const float*)d_in[6];
    const float* sb3 = (const float*)d_in[7];
    const float* jW1 = (const float*)d_in[8];
    const float* jb1 = (const float*)d_in[9];
    const float* jW2 = (const float*)d_in[10];
    const float* jb2 = (const float*)d_in[11];
    const float* jW3 = (const float*)d_in[12];
    const float* jb3 = (const float*)d_in[13];
    float* out = (float*)d_out;

    float *pa = nullptr, *pb = nullptr;
    cudaGetSymbolAddress((void**)&pa, g_bufA);
    cudaGetSymbolAddress((void**)&pb, g_bufB);

    int dev = 0, sms = 148;
    cudaGetDevice(&dev);
    cudaDeviceGetAttribute(&sms, cudaDevAttrMultiProcessorCount, dev);

    int smem32 = smem_bytes(32), smem96 = smem_bytes(96);
    cudaFuncSetAttribute(mlp_mma<32>, cudaFuncAttributeMaxDynamicSharedMemorySize, smem32);
    cudaFuncSetAttribute(mlp_mma<96>, cudaFuncAttributeMaxDynamicSharedMemorySize, smem96);

    // Leaf level: (B*1024, 32) -> bufA as (B, 1024, 32)
    {
        int tiles = (BATCH * NLEAF) / 128;
        int grid = tiles < sms ? tiles : sms;
        mlp_mma<32><<<grid, 256, smem32>>>(leaf_feats, nullptr,
                                           sW1, sb1, sW2, sb2, sW3, sb3,
                                           pa, NLEAF, 10, 0, tiles);
    }

    // Join levels: n = 512 .. 1
    const float* prev = pa;
    float* curb = pb;
    int off = 0;
    for (int n = NLEAF / 2, ln = 9; n >= 1; n >>= 1, --ln) {
        int tiles = (BATCH * n) / 128;
        int grid = tiles < sms ? tiles : sms;
        mlp_mma<96><<<grid, 256, smem96>>>(internal_feats, prev,
                                           jW1, jb1, jW2, jb2, jW3, jb3,
                                           curb, n, ln, off, tiles);
        off += n;
        const float* tmp = curb;
        curb = (float*)prev;
        prev = tmp;
    }

    gather_kernel<<<(BATCH + 255) / 256, 256>>>(prev, out);
}

// round 10
// speedup vs baseline: 6.9265x; 1.8728x over previous
#include <cuda_runtime.h>
#include <cuda_fp16.h>
#include <cstdint>

// ---------------------------------------------------------------------------
// PlanStructuredNetwork via warp-level fp16 mma.sync (sm_103-safe baseline PTX).
// 2-term split: x = xh + xl (fp16 pair), w = fp16 single copy.
//   out = xh*w + xl*w  (fp32 accumulate)  -> per-layer err ~2^-12 from w only.
// Fully warp-independent 16-row strips: layer-1 A fragments loaded straight
// from global into registers (no staging SMEM, no block syncs in the loop);
// L1->L2->L3 chained in registers (mma D layout == next A layout).
// Weights (fp16) + biases live in SMEM, loaded once per persistent CTA.
// ---------------------------------------------------------------------------

#define BATCH 2048
#define NLEAF 1024
#define NW 12   // warps per CTA

__device__ float g_bufA[(size_t)BATCH * NLEAF * 32];       // 256 MB
__device__ float g_bufB[(size_t)BATCH * (NLEAF / 2) * 32]; // 128 MB

__device__ __forceinline__ uint32_t smem_u32(const void* p) {
    uint32_t a;
    asm("{ .reg .u64 t; cvta.to.shared.u64 t, %1; cvt.u32.u64 %0, t; }"
        : "=r"(a) : "l"(p));
    return a;
}

__device__ __forceinline__ void ldsm4(uint32_t addr, uint32_t& r0, uint32_t& r1,
                                      uint32_t& r2, uint32_t& r3) {
    asm volatile("ldmatrix.sync.aligned.m8n8.x4.shared.b16 {%0,%1,%2,%3}, [%4];"
                 : "=r"(r0), "=r"(r1), "=r"(r2), "=r"(r3) : "r"(addr));
}

__device__ __forceinline__ void mma16816(float* d, const uint32_t* a,
                                         uint32_t b0, uint32_t b1) {
    asm volatile(
        "mma.sync.aligned.m16n8k16.row.col.f32.f16.f16.f32 "
        "{%0,%1,%2,%3}, {%4,%5,%6,%7}, {%8,%9}, {%0,%1,%2,%3};"
        : "+f"(d[0]), "+f"(d[1]), "+f"(d[2]), "+f"(d[3])
        : "r"(a[0]), "r"(a[1]), "r"(a[2]), "r"(a[3]), "r"(b0), "r"(b1));
}

// split (a,b) -> fp16 hi pair + fp16 residual-lo pair
__device__ __forceinline__ void pack_split(float a, float b, uint32_t& hi, uint32_t& lo) {
    __half2 hp = __floats2half2_rn(a, b);
    hi = *reinterpret_cast<uint32_t*>(&hp);
    float2 back = __half22float2(hp);
    __half2 lp = __floats2half2_rn(a - back.x, b - back.y);
    lo = *reinterpret_cast<uint32_t*>(&lp);
}

// D(acc) + bias [-> relu] -> next-layer A fragments (hi/lo), registers only.
template <bool RELU>
__device__ __forceinline__ void epi(const float (&acc)[16][4],
                                    uint32_t (&ah)[8][4], uint32_t (&al)[8][4],
                                    const float* __restrict__ bias, int lane4) {
#pragma unroll
    for (int j = 0; j < 16; j++) {
        float2 bb = *(const float2*)(bias + 8 * j + lane4);
        float c0 = acc[j][0] + bb.x, c1 = acc[j][1] + bb.y;
        float c2 = acc[j][2] + bb.x, c3 = acc[j][3] + bb.y;
        if (RELU) {
            c0 = fmaxf(c0, 0.f); c1 = fmaxf(c1, 0.f);
            c2 = fmaxf(c2, 0.f); c3 = fmaxf(c3, 0.f);
        }
        const int s = j >> 1, o = (j & 1) * 2;
        pack_split(c0, c1, ah[s][o], al[s][o]);
        pack_split(c2, c3, ah[s][o + 1], al[s][o + 1]);
    }
}

template <int K>
__global__ void __launch_bounds__(32 * NW, 1)
mlp_mma(const float* __restrict__ feats, const float* __restrict__ prev,
        const float* __restrict__ gW1, const float* __restrict__ gb1,
        const float* __restrict__ gW2, const float* __restrict__ gb2,
        const float* __restrict__ gW3, const float* __restrict__ gb3,
        float* __restrict__ outp, int n, int ln, int offv, int num_strips) {
    constexpr int SA = K + 8;   // halves/row for W1 (odd multiple of 8 -> conflict-free)
    constexpr int S2 = 136;     // halves/row for W2, W3
    constexpr int S1 = K / 16;  // layer-1 k-steps
    constexpr int O_W1 = 0;
    constexpr int O_W2 = O_W1 + 128 * SA;
    constexpr int O_W3 = O_W2 + 128 * S2;
    constexpr int O_BIAS = O_W3 + 32 * S2;

    extern __shared__ __half sh[];
    float* bs = (float*)(sh + O_BIAS);  // [0..127]=b1 [128..255]=b2 [256..287]=b3
    const int tid = threadIdx.x;
    const int lane = tid & 31;
    const int wid = tid >> 5;
    constexpr int NT = 32 * NW;

    // ---- stage weights transposed (Wt[n][k]) as single fp16 ----------------
    for (int idx = tid; idx < 128 * K; idx += NT) {
        int nn = idx & 127, kk = idx >> 7;
        sh[O_W1 + nn * SA + kk] = __float2half(gW1[kk * 128 + nn]);
    }
    for (int idx = tid; idx < 128 * 128; idx += NT) {
        int nn = idx & 127, kk = idx >> 7;
        sh[O_W2 + nn * S2 + kk] = __float2half(gW2[kk * 128 + nn]);
    }
    for (int idx = tid; idx < 32 * 128; idx += NT) {
        int nn = idx & 31, kk = idx >> 5;
        sh[O_W3 + nn * S2 + kk] = __float2half(gW3[kk * 32 + nn]);
    }
    if (tid < 128) { bs[tid] = gb1[tid]; bs[128 + tid] = gb2[tid]; }
    if (tid < 32)  bs[256 + tid] = gb3[tid];
    __syncthreads();

    const uint32_t sb = smem_u32(sh);
    const int lane4 = (lane & 3) * 2;
    // B-ldmatrix lane geometry (mats: n 0-7/8-15 x k 0-7/8-15)
    const int bnr = (lane & 7) + ((lane >> 4) & 1) * 8;
    const int bkb = ((lane >> 3) & 1) * 8;  // halves
    const uint32_t w1b = sb + (O_W1 + bnr * SA + bkb) * 2;
    const uint32_t w2b = sb + (O_W2 + bnr * S2 + bkb) * 2;
    const uint32_t w3b = sb + (O_W3 + bnr * S2 + bkb) * 2;

    float acc[16][4];
    uint32_t ah[8][4], al[8][4];

    for (int st = blockIdx.x * NW + wid; st < num_strips; st += gridDim.x * NW) {
        const long row0g = (long)st * 16;
        const long r0 = row0g + (lane >> 2);  // this lane's low row
        const long r1 = r0 + 8;               // high row

        // ---- layer-1 A fragments straight from global ----------------------
        uint32_t ah1[S1][4], al1[S1][4];
        {
            const float *p0a, *p1a;            // cols 0..31 base (feats)
            const float *p0b = nullptr, *p1b = nullptr;  // cols 32.. base (prev)
            if constexpr (K == 32) {
                p0a = feats + r0 * 32;
                p1a = feats + r1 * 32;
            } else {
                int b0i = (int)(r0 >> ln), i0 = (int)(r0 & (long)(n - 1));
                int b1i = (int)(r1 >> ln), i1 = (int)(r1 & (long)(n - 1));
                p0a = feats + ((long)b0i * (NLEAF - 1) + offv + i0) * 32;
                p1a = feats + ((long)b1i * (NLEAF - 1) + offv + i1) * 32;
                p0b = prev + ((long)b0i * n + i0) * 64 - 32;
                p1b = prev + ((long)b1i * n + i1) * 64 - 32;
            }
#pragma unroll
            for (int s = 0; s < S1; s++) {
                const int c = 16 * s + lane4;
                const float* q0 = (c < 32) ? p0a : p0b;
                const float* q1 = (c < 32) ? p1a : p1b;
                float2 v0 = *(const float2*)(q0 + c);
                float2 v1 = *(const float2*)(q1 + c);
                float2 v2 = *(const float2*)(q0 + c + 8);
                float2 v3 = *(const float2*)(q1 + c + 8);
                pack_split(v0.x, v0.y, ah1[s][0], al1[s][0]);
                pack_split(v1.x, v1.y, ah1[s][1], al1[s][1]);
                pack_split(v2.x, v2.y, ah1[s][2], al1[s][2]);
                pack_split(v3.x, v3.y, ah1[s][3], al1[s][3]);
            }
        }

        // ---- layer 1 -------------------------------------------------------
#pragma unroll
        for (int j = 0; j < 16; j++) {
            acc[j][0] = 0.f; acc[j][1] = 0.f; acc[j][2] = 0.f; acc[j][3] = 0.f;
        }
#pragma unroll
        for (int s = 0; s < S1; s++) {
#pragma unroll
            for (int j2 = 0; j2 < 8; j2++) {
                uint32_t b0, b1, b2, b3;
                ldsm4(w1b + (16 * j2 * SA + 16 * s) * 2, b0, b1, b2, b3);
                mma16816(acc[2 * j2],     ah1[s], b0, b1);
                mma16816(acc[2 * j2 + 1], ah1[s], b2, b3);
                mma16816(acc[2 * j2],     al1[s], b0, b1);
                mma16816(acc[2 * j2 + 1], al1[s], b2, b3);
            }
        }
        epi<true>(acc, ah, al, bs, lane4);

        // ---- layer 2 -------------------------------------------------------
#pragma unroll
        for (int j = 0; j < 16; j++) {
            acc[j][0] = 0.f; acc[j][1] = 0.f; acc[j][2] = 0.f; acc[j][3] = 0.f;
        }
#pragma unroll
        for (int s = 0; s < 8; s++) {
#pragma unroll
            for (int j2 = 0; j2 < 8; j2++) {
                uint32_t b0, b1, b2, b3;
                ldsm4(w2b + (16 * j2 * S2 + 16 * s) * 2, b0, b1, b2, b3);
                mma16816(acc[2 * j2],     ah[s], b0, b1);
                mma16816(acc[2 * j2 + 1], ah[s], b2, b3);
                mma16816(acc[2 * j2],     al[s], b0, b1);
                mma16816(acc[2 * j2 + 1], al[s], b2, b3);
            }
        }
        epi<true>(acc, ah, al, bs + 128, lane4);

        // ---- layer 3: N=32, no relu, fp32 -> global ------------------------
#pragma unroll
        for (int j = 0; j < 4; j++) {
            acc[j][0] = 0.f; acc[j][1] = 0.f; acc[j][2] = 0.f; acc[j][3] = 0.f;
        }
#pragma unroll
        for (int s = 0; s < 8; s++) {
#pragma unroll
            for (int j2 = 0; j2 < 2; j2++) {
                uint32_t b0, b1, b2, b3;
                ldsm4(w3b + (16 * j2 * S2 + 16 * s) * 2, b0, b1, b2, b3);
                mma16816(acc[2 * j2],     ah[s], b0, b1);
                mma16816(acc[2 * j2 + 1], ah[s], b2, b3);
                mma16816(acc[2 * j2],     al[s], b0, b1);
                mma16816(acc[2 * j2 + 1], al[s], b2, b3);
            }
        }
#pragma unroll
        for (int j = 0; j < 4; j++) {
            float2 bb = *(const float2*)(bs + 256 + 8 * j + lane4);
            *(float2*)(outp + r0 * 32 + 8 * j + lane4) =
                make_float2(acc[j][0] + bb.x, acc[j][1] + bb.y);
            *(float2*)(outp + r1 * 32 + 8 * j + lane4) =
                make_float2(acc[j][2] + bb.x, acc[j][3] + bb.y);
        }
    }
}

__global__ void gather_kernel(const float* __restrict__ src, float* __restrict__ dst) {
    int i = blockIdx.x * blockDim.x + threadIdx.x;
    if (i < BATCH) dst[i] = src[(long)i * 32];
}

static int smem_bytes(int K) {
    int halves = 128 * (K + 8) + 128 * 136 + 32 * 136;
    return halves * 2 + 288 * 4;
}

extern "C" void kernel_launch(void* const* d_in, const int* in_sizes, int n_in,
                              void* d_out, int out_size) {
    (void)in_sizes; (void)n_in; (void)out_size;
    const float* leaf_feats     = (const float*)d_in[0];
    const float* internal_feats = (const float*)d_in[1];
    const float* sW1 = (const float*)d_in[2];
    const float* sb1 = (const float*)d_in[3];
    const float* sW2 = (const float*)d_in[4];
    const float* sb2 = (const float*)d_in[5];
    const float* sW3 = (const float*)d_in[6];
    const float* sb3 = (const float*)d_in[7];
    const float* jW1 = (const float*)d_in[8];
    const float* jb1 = (const float*)d_in[9];
    const float* jW2 = (const float*)d_in[10];
    const float* jb2 = (const float*)d_in[11];
    const float* jW3 = (const float*)d_in[12];
    const float* jb3 = (const float*)d_in[13];
    float* out = (float*)d_out;

    float *pa = nullptr, *pb = nullptr;
    cudaGetSymbolAddress((void**)&pa, g_bufA);
    cudaGetSymbolAddress((void**)&pb, g_bufB);

    int dev = 0, sms = 148;
    cudaGetDevice(&dev);
    cudaDeviceGetAttribute(&sms, cudaDevAttrMultiProcessorCount, dev);

    int smem32 = smem_bytes(32), smem96 = smem_bytes(96);
    cudaFuncSetAttribute(mlp_mma<32>, cudaFuncAttributeMaxDynamicSharedMemorySize, smem32);
    cudaFuncSetAttribute(mlp_mma<96>, cudaFuncAttributeMaxDynamicSharedMemorySize, smem96);

    // Leaf level: (B*1024, 32) -> bufA as (B, 1024, 32)
    {
        int strips = (BATCH * NLEAF) / 16;
        int grid = sms;
        mlp_mma<32><<<grid, 32 * NW, smem32>>>(leaf_feats, nullptr,
                                               sW1, sb1, sW2, sb2, sW3, sb3,
                                               pa, NLEAF, 10, 0, strips);
    }

    // Join levels: n = 512 .. 1
    const float* prev = pa;
    float* curb = pb;
    int off = 0;
    for (int n = NLEAF / 2, ln = 9; n >= 1; n >>= 1, --ln) {
        int strips = (BATCH * n) / 16;
        int grid = sms;
        mlp_mma<96><<<grid, 32 * NW, smem96>>>(internal_feats, prev,
                                               jW1, jb1, jW2, jb2, jW3, jb3,
                                               curb, n, ln, off, strips);
        off += n;
        const float* tmp = curb;
        curb = (float*)prev;
        prev = tmp;
    }

    gather_kernel<<<(BATCH + 255) / 256, 256>>>(prev, out);
}